// round 6
// baseline (speedup 1.0000x reference)
#include <cuda_runtime.h>
#include <cstdint>

// Problem constants
#define Bn  4
#define Sn  2048
#define Dn  1024
#define Hn  16
#define DKn 64
#define Mn  (Bn * Sn)   // 8192

// Scratch (allocation-free: __device__ globals)
__device__ float g_Q[(size_t)Bn * Hn * Sn * DKn];     // [B,H,S,DK]
__device__ float g_K[(size_t)Bn * Hn * Sn * DKn];     // [B,H,S,DK]
__device__ float g_V[(size_t)Bn * Hn * Sn * DKn];     // [B,H,S,DK]
__device__ float g_attn[(size_t)Bn * Sn * Dn];        // [B,S,D]

// ---------------------------------------------------------------------------
// Fast exp on the FMA pipe (avoids MUFU.EX2 throughput wall: 268M exps).
// Valid for x <= 0 (softmax arguments). Rel err ~1e-7.
// ---------------------------------------------------------------------------
__device__ __forceinline__ float fast_exp(float x) {
    float t = x * 1.44269504088896341f;          // x * log2(e)
    t = fmaxf(t, -126.0f);                       // clamp (masked -1e9 path)
    float z = t + 12582912.0f;                   // round-to-nearest-int trick
    int   e = __float_as_int(z) - 0x4B400000;    // integer part
    float fi = z - 12582912.0f;
    float f = t - fi;                            // f in [-0.5, 0.5]
    float p = 1.54035303933e-4f;
    p = fmaf(p, f, 1.33335581464e-3f);
    p = fmaf(p, f, 9.61812910763e-3f);
    p = fmaf(p, f, 5.55041086648e-2f);
    p = fmaf(p, f, 2.40226506959e-1f);
    p = fmaf(p, f, 6.93147180560e-1f);
    p = fmaf(p, f, 1.0f);
    return p * __int_as_float((e + 127) << 23);  // * 2^e
}

// ---------------------------------------------------------------------------
// tf32 helpers (3xTF32 split for fp32-accurate tensor-core GEMM)
// ---------------------------------------------------------------------------
__device__ __forceinline__ uint32_t tf32_rna(float x) {
    uint32_t r;
    asm("cvt.rna.tf32.f32 %0, %1;" : "=r"(r) : "f"(x));
    return r;
}

__device__ __forceinline__ void mma_tf32(float* d, const uint32_t* a,
                                         const uint32_t* b) {
    asm volatile(
        "mma.sync.aligned.m16n8k8.row.col.f32.tf32.tf32.f32 "
        "{%0,%1,%2,%3}, {%4,%5,%6,%7}, {%8,%9}, {%0,%1,%2,%3};\n"
        : "+f"(d[0]), "+f"(d[1]), "+f"(d[2]), "+f"(d[3])
        : "r"(a[0]), "r"(a[1]), "r"(a[2]), "r"(a[3]),
          "r"(b[0]), "r"(b[1]));
}

// ---------------------------------------------------------------------------
// GEMM: C[M,N] = A[M,K] @ W[N,K]^T + bias   via mma.sync m16n8k8 tf32,
// 3-term split (Ah*Wh + Ah*Wl + Al*Wh) for ~fp32 accuracy at K=1024.
// 128x128 block tile, BK=16, 256 threads, 8 warps as 2(M)x4(N) of 64x32.
// Smem row stride 20 floats: frag LDS bank-perm conflict-free, STS.128 optimal.
// MODE 1: A = input, write remapped to g_Q/g_K/g_V as [B,H,S,DK]
// MODE 0: A = g_attn, write plain [M,N] to outp (final projection)
// ---------------------------------------------------------------------------
#define SKW 20   // smem stride (floats) for 16-wide K panel

template <int MODE>
__global__ __launch_bounds__(256) void gemm_k(const float* __restrict__ Ain,
                                              const float* __restrict__ W,
                                              const float* __restrict__ bias,
                                              float* __restrict__ outp,
                                              int which) {
    __shared__ __align__(16) uint32_t Ah[128 * SKW];
    __shared__ __align__(16) uint32_t Al[128 * SKW];
    __shared__ __align__(16) uint32_t Wh[128 * SKW];
    __shared__ __align__(16) uint32_t Wl[128 * SKW];

    const int tid  = threadIdx.x;
    const int lane = tid & 31;
    const int w    = tid >> 5;
    const int wm   = w >> 2;          // 0..1  (64-row slab)
    const int wn   = w & 3;           // 0..3  (32-col slab)
    const int g    = lane >> 2;       // 0..7
    const int c    = lane & 3;        // 0..3
    const int m0   = blockIdx.y << 7;
    const int n0   = blockIdx.x << 7;

    const float* A = (MODE == 0) ? g_attn : Ain;

    float acc[4][4][4];
#pragma unroll
    for (int mt = 0; mt < 4; mt++)
#pragma unroll
        for (int nt = 0; nt < 4; nt++)
#pragma unroll
            for (int r = 0; r < 4; r++) acc[mt][nt][r] = 0.f;

    const int lrow = tid >> 2;        // 0..63  (+64 on second pass)
    const int lq   = (tid & 3) << 2;  // k offset 0,4,8,12

    for (int k0 = 0; k0 < Dn; k0 += 16) {
        __syncthreads();   // previous compute done before overwrite
#pragma unroll
        for (int i = 0; i < 2; i++) {
            int row = lrow + (i << 6);
            float4 a = *(const float4*)(A + (size_t)(m0 + row) * Dn + k0 + lq);
            uint4 h4, l4;
            h4.x = tf32_rna(a.x); l4.x = tf32_rna(a.x - __uint_as_float(h4.x));
            h4.y = tf32_rna(a.y); l4.y = tf32_rna(a.y - __uint_as_float(h4.y));
            h4.z = tf32_rna(a.z); l4.z = tf32_rna(a.z - __uint_as_float(h4.z));
            h4.w = tf32_rna(a.w); l4.w = tf32_rna(a.w - __uint_as_float(h4.w));
            *(uint4*)&Ah[row * SKW + lq] = h4;
            *(uint4*)&Al[row * SKW + lq] = l4;

            float4 b = *(const float4*)(W + (size_t)(n0 + row) * Dn + k0 + lq);
            h4.x = tf32_rna(b.x); l4.x = tf32_rna(b.x - __uint_as_float(h4.x));
            h4.y = tf32_rna(b.y); l4.y = tf32_rna(b.y - __uint_as_float(h4.y));
            h4.z = tf32_rna(b.z); l4.z = tf32_rna(b.z - __uint_as_float(h4.z));
            h4.w = tf32_rna(b.w); l4.w = tf32_rna(b.w - __uint_as_float(h4.w));
            *(uint4*)&Wh[row * SKW + lq] = h4;
            *(uint4*)&Wl[row * SKW + lq] = l4;
        }
        __syncthreads();

#pragma unroll
        for (int kk = 0; kk < 16; kk += 8) {
            uint32_t a_h[4][4], a_l[4][4], b_h[4][2], b_l[4][2];
#pragma unroll
            for (int mt = 0; mt < 4; mt++) {
                int base = ((wm << 6) + (mt << 4) + g) * SKW + kk + c;
                a_h[mt][0] = Ah[base];           a_h[mt][1] = Ah[base + 8 * SKW];
                a_h[mt][2] = Ah[base + 4];       a_h[mt][3] = Ah[base + 8 * SKW + 4];
                a_l[mt][0] = Al[base];           a_l[mt][1] = Al[base + 8 * SKW];
                a_l[mt][2] = Al[base + 4];       a_l[mt][3] = Al[base + 8 * SKW + 4];
            }
#pragma unroll
            for (int nt = 0; nt < 4; nt++) {
                int base = ((wn << 5) + (nt << 3) + g) * SKW + kk + c;
                b_h[nt][0] = Wh[base];           b_h[nt][1] = Wh[base + 4];
                b_l[nt][0] = Wl[base];           b_l[nt][1] = Wl[base + 4];
            }
#pragma unroll
            for (int mt = 0; mt < 4; mt++)
#pragma unroll
                for (int nt = 0; nt < 4; nt++) {
                    mma_tf32(acc[mt][nt], a_h[mt], b_h[nt]);
                    mma_tf32(acc[mt][nt], a_h[mt], b_l[nt]);
                    mma_tf32(acc[mt][nt], a_l[mt], b_h[nt]);
                }
        }
    }

    // Epilogue: c0,c1 at (row g, cols 2c,2c+1); c2,c3 at (row g+8, same cols)
#pragma unroll
    for (int mt = 0; mt < 4; mt++) {
#pragma unroll
        for (int nt = 0; nt < 4; nt++) {
            int col = n0 + (wn << 5) + (nt << 3) + (c << 1);
            float b0 = bias[col], b1 = bias[col + 1];
#pragma unroll
            for (int half = 0; half < 2; half++) {
                int m = m0 + (wm << 6) + (mt << 4) + g + (half << 3);
                float2 v;
                v.x = acc[mt][nt][half * 2 + 0] + b0;
                v.y = acc[mt][nt][half * 2 + 1] + b1;
                if (MODE == 1) {
                    int bb = m >> 11;
                    int ss = m & (Sn - 1);
                    int h  = col >> 6;
                    int d  = col & 63;
                    float* outg = (which == 0) ? g_Q : (which == 1) ? g_K : g_V;
                    *(float2*)&outg[(((size_t)bb * Hn + h) * Sn + ss) * DKn + d] = v;
                } else {
                    *(float2*)&outp[(size_t)m * Dn + col] = v;
                }
            }
        }
    }
}

// ---------------------------------------------------------------------------
// Flash attention, fp32 SIMT (unchanged, known-good). One block = 64 query
// rows of one (b,h). 256 threads, 4x4 microtile. Rotation-skewed smem.
// ---------------------------------------------------------------------------
__global__ __launch_bounds__(256) void attn_kernel(const int* __restrict__ mask) {
    __shared__ float Qs[64 * 64];
    __shared__ float KPs[64 * 64];
    __shared__ float Vs[64 * 64];

    const int tid = threadIdx.x;
    const int tx = tid & 15;
    const int ty = tid >> 4;
    const int q0 = blockIdx.x << 6;
    const int h  = blockIdx.y;
    const int b  = blockIdx.z;

    const size_t head_off = ((size_t)b * Hn + h) * Sn * DKn;
    const float* Qg = g_Q + head_off + (size_t)q0 * DKn;
    const float* Kg = g_K + head_off;
    const float* Vg = g_V + head_off;
    const int* mrow = mask + (size_t)b * Sn * Sn + (size_t)q0 * Sn;

    const int ri0 = ty << 2;
    const int cj0 = tx << 2;
    const int rotq = (ty & 1) << 4;

#pragma unroll
    for (int i = 0; i < 4; i++) {
        int v = tid + (i << 8);
        int row = v >> 4;
        int c = (v & 15) << 2;
        float4 qv = *(const float4*)(Qg + (size_t)row * DKn + c);
        int rot = ((row >> 2) & 1) << 4;
        Qs[row * 64 + ((c + 0 + rot) & 63)] = qv.x;
        Qs[row * 64 + ((c + 1 + rot) & 63)] = qv.y;
        Qs[row * 64 + ((c + 2 + rot) & 63)] = qv.z;
        Qs[row * 64 + ((c + 3 + rot) & 63)] = qv.w;
    }

    float O[4][4];
    float mx[4], l[4];
#pragma unroll
    for (int i = 0; i < 4; i++) {
        mx[i] = -1e30f; l[i] = 0.f;
#pragma unroll
        for (int j = 0; j < 4; j++) O[i][j] = 0.f;
    }

    for (int kt = 0; kt < Sn / 64; kt++) {
        const int k0 = kt << 6;
        __syncthreads();

#pragma unroll
        for (int i = 0; i < 4; i++) {
            int v = tid + (i << 8);
            int row = v >> 4;
            int c = (v & 15) << 2;
            float4 kv = *(const float4*)(Kg + (size_t)(k0 + row) * DKn + c);
            int rot = row >> 2;
            KPs[row * 64 + ((c + 0 + rot) & 63)] = kv.x;
            KPs[row * 64 + ((c + 1 + rot) & 63)] = kv.y;
            KPs[row * 64 + ((c + 2 + rot) & 63)] = kv.z;
            KPs[row * 64 + ((c + 3 + rot) & 63)] = kv.w;
            *(float4*)&Vs[row * 64 + c] =
                *(const float4*)(Vg + (size_t)(k0 + row) * DKn + c);
        }
        __syncthreads();

        float sA[4][4];
#pragma unroll
        for (int i = 0; i < 4; i++)
#pragma unroll
            for (int j = 0; j < 4; j++) sA[i][j] = 0.f;

#pragma unroll 8
        for (int d = 0; d < 64; d++) {
            int qoff = (d + rotq) & 63;
            int koff = (d + tx) & 63;
            float qv[4], kv[4];
#pragma unroll
            for (int i = 0; i < 4; i++) qv[i] = Qs[(ri0 + i) * 64 + qoff];
#pragma unroll
            for (int j = 0; j < 4; j++) kv[j] = KPs[(cj0 + j) * 64 + koff];
#pragma unroll
            for (int i = 0; i < 4; i++)
#pragma unroll
                for (int j = 0; j < 4; j++)
                    sA[i][j] = fmaf(qv[i], kv[j], sA[i][j]);
        }

        // scale + mask (vector int4 mask loads)
#pragma unroll
        for (int i = 0; i < 4; i++) {
            const int4 mv = *(const int4*)(mrow + (size_t)(ri0 + i) * Sn + k0 + cj0);
            sA[i][0] = (mv.x == 0) ? -1e9f : sA[i][0] * 0.125f;
            sA[i][1] = (mv.y == 0) ? -1e9f : sA[i][1] * 0.125f;
            sA[i][2] = (mv.z == 0) ? -1e9f : sA[i][2] * 0.125f;
            sA[i][3] = (mv.w == 0) ? -1e9f : sA[i][3] * 0.125f;
        }

        float p[4][4];
#pragma unroll
        for (int i = 0; i < 4; i++) {
            float rm = fmaxf(fmaxf(sA[i][0], sA[i][1]), fmaxf(sA[i][2], sA[i][3]));
            rm = fmaxf(rm, __shfl_xor_sync(0xffffffffu, rm, 1));
            rm = fmaxf(rm, __shfl_xor_sync(0xffffffffu, rm, 2));
            rm = fmaxf(rm, __shfl_xor_sync(0xffffffffu, rm, 4));
            rm = fmaxf(rm, __shfl_xor_sync(0xffffffffu, rm, 8));
            float mnew = fmaxf(mx[i], rm);
            float alpha = fast_exp(mx[i] - mnew);
            mx[i] = mnew;
            float rs = 0.f;
#pragma unroll
            for (int j = 0; j < 4; j++) {
                p[i][j] = fast_exp(sA[i][j] - mnew);
                rs += p[i][j];
            }
            rs += __shfl_xor_sync(0xffffffffu, rs, 1);
            rs += __shfl_xor_sync(0xffffffffu, rs, 2);
            rs += __shfl_xor_sync(0xffffffffu, rs, 4);
            rs += __shfl_xor_sync(0xffffffffu, rs, 8);
            l[i] = l[i] * alpha + rs;
#pragma unroll
            for (int j = 0; j < 4; j++) O[i][j] *= alpha;
        }

        __syncthreads();

#pragma unroll
        for (int i = 0; i < 4; i++)
#pragma unroll
            for (int j = 0; j < 4; j++)
                KPs[(ri0 + i) * 64 + ((cj0 + j + rotq) & 63)] = p[i][j];
        __syncthreads();

#pragma unroll 8
        for (int k = 0; k < 64; k++) {
            float4 v4 = *(const float4*)&Vs[k * 64 + cj0];
            int poff = (k + rotq) & 63;
            float pv[4];
#pragma unroll
            for (int i = 0; i < 4; i++) pv[i] = KPs[(ri0 + i) * 64 + poff];
#pragma unroll
            for (int i = 0; i < 4; i++) {
                O[i][0] = fmaf(pv[i], v4.x, O[i][0]);
                O[i][1] = fmaf(pv[i], v4.y, O[i][1]);
                O[i][2] = fmaf(pv[i], v4.z, O[i][2]);
                O[i][3] = fmaf(pv[i], v4.w, O[i][3]);
            }
        }
    }

    float* og = g_attn + ((size_t)b * Sn + q0) * Dn + h * DKn;
#pragma unroll
    for (int i = 0; i < 4; i++) {
        float inv = 1.0f / l[i];
#pragma unroll
        for (int j = 0; j < 4; j++)
            og[(size_t)(ri0 + i) * Dn + cj0 + j] = O[i][j] * inv;
    }
}

// ---------------------------------------------------------------------------
// kernel_launch: 5 kernel launches on the default stream (graph-capturable)
// ---------------------------------------------------------------------------
extern "C" void kernel_launch(void* const* d_in, const int* in_sizes, int n_in,
                              void* d_out, int out_size) {
    (void)in_sizes; (void)n_in; (void)out_size;
    const float* query = (const float*)d_in[0];
    const float* key   = (const float*)d_in[1];
    const float* value = (const float*)d_in[2];
    const int*   mask  = (const int*)d_in[3];
    const float* Wq = (const float*)d_in[4];
    const float* bq = (const float*)d_in[5];
    const float* Wk = (const float*)d_in[6];
    const float* bk = (const float*)d_in[7];
    const float* Wv = (const float*)d_in[8];
    const float* bv = (const float*)d_in[9];
    const float* Wo = (const float*)d_in[10];
    const float* bo = (const float*)d_in[11];

    dim3 gg(Dn / 128, Mn / 128);   // (8, 64)
    gemm_k<1><<<gg, 256>>>(query, Wq, bq, nullptr, 0);
    gemm_k<1><<<gg, 256>>>(key,   Wk, bk, nullptr, 1);
    gemm_k<1><<<gg, 256>>>(value, Wv, bv, nullptr, 2);

    attn_kernel<<<dim3(Sn / 64, Hn, Bn), 256>>>(mask);

    gemm_k<0><<<gg, 256>>>(nullptr, Wo, bo, (float*)d_out, 0);
}

// round 7
// speedup vs baseline: 1.7535x; 1.7535x over previous
#include <cuda_runtime.h>
#include <cstdint>

// Problem constants
#define Bn  4
#define Sn  2048
#define Dn  1024
#define Hn  16
#define DKn 64
#define Mn  (Bn * Sn)   // 8192

// Scratch (allocation-free: __device__ globals)
__device__ float g_Q[(size_t)Bn * Hn * Sn * DKn];     // [B,H,S,DK]
__device__ float g_K[(size_t)Bn * Hn * Sn * DKn];     // [B,H,S,DK]
__device__ float g_V[(size_t)Bn * Hn * Sn * DKn];     // [B,H,DK,S]  (transposed!)
__device__ float g_attn[(size_t)Bn * Sn * Dn];        // [B,S,D]

// ---------------------------------------------------------------------------
// Fast exp on the FMA pipe. Valid for x <= 0. Rel err ~1e-7.
// ---------------------------------------------------------------------------
__device__ __forceinline__ float fast_exp(float x) {
    float t = x * 1.44269504088896341f;
    t = fmaxf(t, -126.0f);
    float z = t + 12582912.0f;
    int   e = __float_as_int(z) - 0x4B400000;
    float fi = z - 12582912.0f;
    float f = t - fi;
    float p = 1.54035303933e-4f;
    p = fmaf(p, f, 1.33335581464e-3f);
    p = fmaf(p, f, 9.61812910763e-3f);
    p = fmaf(p, f, 5.55041086648e-2f);
    p = fmaf(p, f, 2.40226506959e-1f);
    p = fmaf(p, f, 6.93147180560e-1f);
    p = fmaf(p, f, 1.0f);
    return p * __int_as_float((e + 127) << 23);
}

// ---------------------------------------------------------------------------
// tf32 helpers
// ---------------------------------------------------------------------------
__device__ __forceinline__ uint32_t tf32_rna(float x) {
    uint32_t r;
    asm("cvt.rna.tf32.f32 %0, %1;" : "=r"(r) : "f"(x));
    return r;
}

__device__ __forceinline__ void mma_tf32(float* d, const uint32_t* a,
                                         const uint32_t* b) {
    asm volatile(
        "mma.sync.aligned.m16n8k8.row.col.f32.tf32.tf32.f32 "
        "{%0,%1,%2,%3}, {%4,%5,%6,%7}, {%8,%9}, {%0,%1,%2,%3};\n"
        : "+f"(d[0]), "+f"(d[1]), "+f"(d[2]), "+f"(d[3])
        : "r"(a[0]), "r"(a[1]), "r"(a[2]), "r"(a[3]),
          "r"(b[0]), "r"(b[1]));
}

__device__ __forceinline__ void mma_tf32_b(float* d, const uint32_t* a,
                                           uint32_t b0, uint32_t b1) {
    asm volatile(
        "mma.sync.aligned.m16n8k8.row.col.f32.tf32.tf32.f32 "
        "{%0,%1,%2,%3}, {%4,%5,%6,%7}, {%8,%9}, {%0,%1,%2,%3};\n"
        : "+f"(d[0]), "+f"(d[1]), "+f"(d[2]), "+f"(d[3])
        : "r"(a[0]), "r"(a[1]), "r"(a[2]), "r"(a[3]),
          "r"(b0), "r"(b1));
}

// ---------------------------------------------------------------------------
// GEMM: C[M,N] = A[M,K] @ W[N,K]^T + bias  via mma tf32 (3x split, fp32-acc).
// 128x128 block tile, BK=16, 256 threads, 8 warps as 2(M)x4(N) of 64x32.
// MODE 1: write remapped: which 0->g_Q [B,H,S,DK], 1->g_K [B,H,S,DK],
//                         which 2->g_V TRANSPOSED [B,H,DK,S]
// MODE 0: A = g_attn, write plain [M,N] to outp (final projection)
// ---------------------------------------------------------------------------
#define SKW 20

template <int MODE>
__global__ __launch_bounds__(256) void gemm_k(const float* __restrict__ Ain,
                                              const float* __restrict__ W,
                                              const float* __restrict__ bias,
                                              float* __restrict__ outp,
                                              int which) {
    __shared__ __align__(16) uint32_t Ah[128 * SKW];
    __shared__ __align__(16) uint32_t Al[128 * SKW];
    __shared__ __align__(16) uint32_t Wh[128 * SKW];
    __shared__ __align__(16) uint32_t Wl[128 * SKW];

    const int tid  = threadIdx.x;
    const int lane = tid & 31;
    const int w    = tid >> 5;
    const int wm   = w >> 2;
    const int wn   = w & 3;
    const int g    = lane >> 2;
    const int c    = lane & 3;
    const int m0   = blockIdx.y << 7;
    const int n0   = blockIdx.x << 7;

    const float* A = (MODE == 0) ? g_attn : Ain;

    float acc[4][4][4];
#pragma unroll
    for (int mt = 0; mt < 4; mt++)
#pragma unroll
        for (int nt = 0; nt < 4; nt++)
#pragma unroll
            for (int r = 0; r < 4; r++) acc[mt][nt][r] = 0.f;

    const int lrow = tid >> 2;
    const int lq   = (tid & 3) << 2;

    for (int k0 = 0; k0 < Dn; k0 += 16) {
        __syncthreads();
#pragma unroll
        for (int i = 0; i < 2; i++) {
            int row = lrow + (i << 6);
            float4 a = *(const float4*)(A + (size_t)(m0 + row) * Dn + k0 + lq);
            uint4 h4, l4;
            h4.x = tf32_rna(a.x); l4.x = tf32_rna(a.x - __uint_as_float(h4.x));
            h4.y = tf32_rna(a.y); l4.y = tf32_rna(a.y - __uint_as_float(h4.y));
            h4.z = tf32_rna(a.z); l4.z = tf32_rna(a.z - __uint_as_float(h4.z));
            h4.w = tf32_rna(a.w); l4.w = tf32_rna(a.w - __uint_as_float(h4.w));
            *(uint4*)&Ah[row * SKW + lq] = h4;
            *(uint4*)&Al[row * SKW + lq] = l4;

            float4 b = *(const float4*)(W + (size_t)(n0 + row) * Dn + k0 + lq);
            h4.x = tf32_rna(b.x); l4.x = tf32_rna(b.x - __uint_as_float(h4.x));
            h4.y = tf32_rna(b.y); l4.y = tf32_rna(b.y - __uint_as_float(h4.y));
            h4.z = tf32_rna(b.z); l4.z = tf32_rna(b.z - __uint_as_float(h4.z));
            h4.w = tf32_rna(b.w); l4.w = tf32_rna(b.w - __uint_as_float(h4.w));
            *(uint4*)&Wh[row * SKW + lq] = h4;
            *(uint4*)&Wl[row * SKW + lq] = l4;
        }
        __syncthreads();

#pragma unroll
        for (int kk = 0; kk < 16; kk += 8) {
            uint32_t a_h[4][4], a_l[4][4], b_h[4][2], b_l[4][2];
#pragma unroll
            for (int mt = 0; mt < 4; mt++) {
                int base = ((wm << 6) + (mt << 4) + g) * SKW + kk + c;
                a_h[mt][0] = Ah[base];           a_h[mt][1] = Ah[base + 8 * SKW];
                a_h[mt][2] = Ah[base + 4];       a_h[mt][3] = Ah[base + 8 * SKW + 4];
                a_l[mt][0] = Al[base];           a_l[mt][1] = Al[base + 8 * SKW];
                a_l[mt][2] = Al[base + 4];       a_l[mt][3] = Al[base + 8 * SKW + 4];
            }
#pragma unroll
            for (int nt = 0; nt < 4; nt++) {
                int base = ((wn << 5) + (nt << 3) + g) * SKW + kk + c;
                b_h[nt][0] = Wh[base];           b_h[nt][1] = Wh[base + 4];
                b_l[nt][0] = Wl[base];           b_l[nt][1] = Wl[base + 4];
            }
#pragma unroll
            for (int mt = 0; mt < 4; mt++)
#pragma unroll
                for (int nt = 0; nt < 4; nt++) {
                    mma_tf32(acc[mt][nt], a_h[mt], b_h[nt]);
                    mma_tf32(acc[mt][nt], a_h[mt], b_l[nt]);
                    mma_tf32(acc[mt][nt], a_l[mt], b_h[nt]);
                }
        }
    }

#pragma unroll
    for (int mt = 0; mt < 4; mt++) {
#pragma unroll
        for (int nt = 0; nt < 4; nt++) {
            int col = n0 + (wn << 5) + (nt << 3) + (c << 1);
            float b0 = bias[col], b1 = bias[col + 1];
#pragma unroll
            for (int half = 0; half < 2; half++) {
                int m = m0 + (wm << 6) + (mt << 4) + g + (half << 3);
                float vx = acc[mt][nt][half * 2 + 0] + b0;
                float vy = acc[mt][nt][half * 2 + 1] + b1;
                if (MODE == 1) {
                    int bb = m >> 11;
                    int ss = m & (Sn - 1);
                    int h  = col >> 6;
                    int d  = col & 63;
                    if (which == 2) {
                        // transposed: [B,H,DK,S]
                        float* outg = g_V;
                        outg[(((size_t)bb * Hn + h) * DKn + d) * Sn + ss] = vx;
                        outg[(((size_t)bb * Hn + h) * DKn + d + 1) * Sn + ss] = vy;
                    } else {
                        float* outg = (which == 0) ? g_Q : g_K;
                        float2 v = {vx, vy};
                        *(float2*)&outg[(((size_t)bb * Hn + h) * Sn + ss) * DKn + d] = v;
                    }
                } else {
                    float2 v = {vx, vy};
                    *(float2*)&outp[(size_t)m * Dn + col] = v;
                }
            }
        }
    }
}

// ---------------------------------------------------------------------------
// Flash attention on tensor cores (tf32 mma, single-pass).
// Block = 128 q rows of one (b,h); 8 warps, each owns 16 q rows (m16).
// 32 K-tiles of 64. K tile [kv][d] and V tile [d][kv] in smem, stride 68
// (frag LDS banks (4g+c)%32 — conflict-free). Q fragments register-resident.
// P fragments built from S C-fragments via quad shuffles (no P smem).
// ---------------------------------------------------------------------------
#define VSTR 68

__global__ __launch_bounds__(256, 2) void attn_kernel(const int* __restrict__ mask) {
    __shared__ __align__(16) uint32_t Ks[64 * VSTR];
    __shared__ __align__(16) uint32_t Vs[64 * VSTR];

    const int tid  = threadIdx.x;
    const int lane = tid & 31;
    const int w    = tid >> 5;
    const int g    = lane >> 2;
    const int c    = lane & 3;
    const int q0   = blockIdx.x << 7;   // 128 q rows per block
    const int h    = blockIdx.y;
    const int b    = blockIdx.z;

    const size_t head_off = ((size_t)b * Hn + h) * (size_t)Sn * DKn;
    const float* Qg = g_Q + head_off;
    const float* Kg = g_K + head_off;
    const float* Vg = g_V + head_off;              // [DK][S]
    const int rowA = q0 + w * 16 + g;
    const int rowB = rowA + 8;
    const int* mAp = mask + (size_t)b * Sn * Sn + (size_t)rowA * Sn;
    const int* mBp = mAp + 8 * Sn;

    // Q fragments (tf32), loaded once, reused across all 32 K-tiles
    uint32_t qf[8][4];
#pragma unroll
    for (int ks = 0; ks < 8; ks++) {
        qf[ks][0] = tf32_rna(Qg[(size_t)rowA * DKn + ks * 8 + c]);
        qf[ks][1] = tf32_rna(Qg[(size_t)rowB * DKn + ks * 8 + c]);
        qf[ks][2] = tf32_rna(Qg[(size_t)rowA * DKn + ks * 8 + c + 4]);
        qf[ks][3] = tf32_rna(Qg[(size_t)rowB * DKn + ks * 8 + c + 4]);
    }

    float O[8][4];
#pragma unroll
    for (int nb = 0; nb < 8; nb++)
#pragma unroll
        for (int r = 0; r < 4; r++) O[nb][r] = 0.f;
    float mxA = -1e30f, mxB = -1e30f, lA = 0.f, lB = 0.f;

    for (int kt = 0; kt < Sn / 64; kt++) {
        const int k0 = kt << 6;
        __syncthreads();   // previous iter's frag reads complete

        // Load K tile [kv][d] and V tile [d][kv] (tf32-converted, stride 68)
#pragma unroll
        for (int i = 0; i < 4; i++) {
            int idx = tid + (i << 8);
            int r  = idx >> 4;
            int f4 = (idx & 15) << 2;
            float4 k4 = *(const float4*)(Kg + (size_t)(k0 + r) * DKn + f4);
            uint4 uk;
            uk.x = tf32_rna(k4.x); uk.y = tf32_rna(k4.y);
            uk.z = tf32_rna(k4.z); uk.w = tf32_rna(k4.w);
            *(uint4*)&Ks[r * VSTR + f4] = uk;
            float4 v4 = *(const float4*)(Vg + (size_t)r * Sn + k0 + f4);
            uint4 uv;
            uv.x = tf32_rna(v4.x); uv.y = tf32_rna(v4.y);
            uv.z = tf32_rna(v4.z); uv.w = tf32_rna(v4.w);
            *(uint4*)&Vs[r * VSTR + f4] = uv;
        }
        __syncthreads();

        // S = Q @ K^T : per warp 16x64 in 8 n-blocks
        float sa[8][4];
#pragma unroll
        for (int nb = 0; nb < 8; nb++)
#pragma unroll
            for (int r = 0; r < 4; r++) sa[nb][r] = 0.f;

#pragma unroll
        for (int ks = 0; ks < 8; ks++) {
#pragma unroll
            for (int nb = 0; nb < 8; nb++) {
                uint32_t b0 = Ks[(nb * 8 + g) * VSTR + ks * 8 + c];
                uint32_t b1 = Ks[(nb * 8 + g) * VSTR + ks * 8 + c + 4];
                mma_tf32_b(sa[nb], qf[ks], b0, b1);
            }
        }

        // Scale + mask + row max (rows: A = g, B = g+8)
        float smA = -1e30f, smB = -1e30f;
#pragma unroll
        for (int nb = 0; nb < 8; nb++) {
            int2 m0 = *(const int2*)(mAp + k0 + nb * 8 + 2 * c);
            int2 m1 = *(const int2*)(mBp + k0 + nb * 8 + 2 * c);
            sa[nb][0] = m0.x ? sa[nb][0] * 0.125f : -1e9f;
            sa[nb][1] = m0.y ? sa[nb][1] * 0.125f : -1e9f;
            sa[nb][2] = m1.x ? sa[nb][2] * 0.125f : -1e9f;
            sa[nb][3] = m1.y ? sa[nb][3] * 0.125f : -1e9f;
            smA = fmaxf(smA, fmaxf(sa[nb][0], sa[nb][1]));
            smB = fmaxf(smB, fmaxf(sa[nb][2], sa[nb][3]));
        }
        smA = fmaxf(smA, __shfl_xor_sync(0xffffffffu, smA, 1));
        smA = fmaxf(smA, __shfl_xor_sync(0xffffffffu, smA, 2));
        smB = fmaxf(smB, __shfl_xor_sync(0xffffffffu, smB, 1));
        smB = fmaxf(smB, __shfl_xor_sync(0xffffffffu, smB, 2));

        float mnA = fmaxf(mxA, smA), mnB = fmaxf(mxB, smB);
        float aA = fast_exp(mxA - mnA), aB = fast_exp(mxB - mnB);
        mxA = mnA; mxB = mnB;

        float rsA = 0.f, rsB = 0.f;
#pragma unroll
        for (int nb = 0; nb < 8; nb++) {
            sa[nb][0] = fast_exp(sa[nb][0] - mnA);
            sa[nb][1] = fast_exp(sa[nb][1] - mnA);
            sa[nb][2] = fast_exp(sa[nb][2] - mnB);
            sa[nb][3] = fast_exp(sa[nb][3] - mnB);
            rsA += sa[nb][0] + sa[nb][1];
            rsB += sa[nb][2] + sa[nb][3];
        }
        rsA += __shfl_xor_sync(0xffffffffu, rsA, 1);
        rsA += __shfl_xor_sync(0xffffffffu, rsA, 2);
        rsB += __shfl_xor_sync(0xffffffffu, rsB, 1);
        rsB += __shfl_xor_sync(0xffffffffu, rsB, 2);
        lA = lA * aA + rsA;
        lB = lB * aB + rsB;

#pragma unroll
        for (int nb = 0; nb < 8; nb++) {
            O[nb][0] *= aA; O[nb][1] *= aA;
            O[nb][2] *= aB; O[nb][3] *= aB;
        }

        // O += P @ V. A-frags of P built from C-frag layout via quad shuffles:
        // C frag holds cols {2c,2c+1}; A frag needs cols {c, c+4}.
        const int srcLo = (lane & 28) | (c >> 1);
        const int srcHi = srcLo + 2;
        const bool odd = (c & 1);
#pragma unroll
        for (int ks = 0; ks < 8; ks++) {
            float v0 = __shfl_sync(0xffffffffu, sa[ks][0], srcLo);
            float v1 = __shfl_sync(0xffffffffu, sa[ks][1], srcLo);
            float v2 = __shfl_sync(0xffffffffu, sa[ks][2], srcLo);
            float v3 = __shfl_sync(0xffffffffu, sa[ks][3], srcLo);
            float w0 = __shfl_sync(0xffffffffu, sa[ks][0], srcHi);
            float w1 = __shfl_sync(0xffffffffu, sa[ks][1], srcHi);
            float w2 = __shfl_sync(0xffffffffu, sa[ks][2], srcHi);
            float w3 = __shfl_sync(0xffffffffu, sa[ks][3], srcHi);
            uint32_t af[4];
            af[0] = tf32_rna(odd ? v1 : v0);   // P[g   ][ks*8+c  ]
            af[1] = tf32_rna(odd ? v3 : v2);   // P[g+8 ][ks*8+c  ]
            af[2] = tf32_rna(odd ? w1 : w0);   // P[g   ][ks*8+c+4]
            af[3] = tf32_rna(odd ? w3 : w2);   // P[g+8 ][ks*8+c+4]
#pragma unroll
            for (int nb = 0; nb < 8; nb++) {
                uint32_t b0 = Vs[(nb * 8 + g) * VSTR + ks * 8 + c];
                uint32_t b1 = Vs[(nb * 8 + g) * VSTR + ks * 8 + c + 4];
                mma_tf32_b(O[nb], af, b0, b1);
            }
        }
    }

    // Epilogue: normalize, write to g_attn [B,S,D]
    const float invA = 1.0f / lA, invB = 1.0f / lB;
    float* ogA = g_attn + ((size_t)b * Sn + rowA) * Dn + h * DKn;
    float* ogB = ogA + 8 * Dn;
#pragma unroll
    for (int nb = 0; nb < 8; nb++) {
        int col = nb * 8 + 2 * c;
        float2 va = {O[nb][0] * invA, O[nb][1] * invA};
        float2 vb = {O[nb][2] * invB, O[nb][3] * invB};
        *(float2*)&ogA[col] = va;
        *(float2*)&ogB[col] = vb;
    }
}

// ---------------------------------------------------------------------------
// kernel_launch: 5 kernel launches on the default stream (graph-capturable)
// ---------------------------------------------------------------------------
extern "C" void kernel_launch(void* const* d_in, const int* in_sizes, int n_in,
                              void* d_out, int out_size) {
    (void)in_sizes; (void)n_in; (void)out_size;
    const float* query = (const float*)d_in[0];
    const float* key   = (const float*)d_in[1];
    const float* value = (const float*)d_in[2];
    const int*   mask  = (const int*)d_in[3];
    const float* Wq = (const float*)d_in[4];
    const float* bq = (const float*)d_in[5];
    const float* Wk = (const float*)d_in[6];
    const float* bk = (const float*)d_in[7];
    const float* Wv = (const float*)d_in[8];
    const float* bv = (const float*)d_in[9];
    const float* Wo = (const float*)d_in[10];
    const float* bo = (const float*)d_in[11];

    dim3 gg(Dn / 128, Mn / 128);   // (8, 64)
    gemm_k<1><<<gg, 256>>>(query, Wq, bq, nullptr, 0);
    gemm_k<1><<<gg, 256>>>(key,   Wk, bk, nullptr, 1);
    gemm_k<1><<<gg, 256>>>(value, Wv, bv, nullptr, 2);

    attn_kernel<<<dim3(Sn / 128, Hn, Bn), 256>>>(mask);

    gemm_k<0><<<gg, 256>>>(nullptr, Wo, bo, (float*)d_out, 0);
}

// round 8
// speedup vs baseline: 3.0289x; 1.7274x over previous
#include <cuda_runtime.h>
#include <cstdint>

// Problem constants
#define Bn  4
#define Sn  2048
#define Dn  1024
#define Hn  16
#define DKn 64
#define Mn  (Bn * Sn)   // 8192

// Scratch (allocation-free: __device__ globals)
__device__ float g_Q[(size_t)Bn * Hn * Sn * DKn];     // [B,H,S,DK]
__device__ float g_K[(size_t)Bn * Hn * Sn * DKn];     // [B,H,S,DK]
__device__ float g_V[(size_t)Bn * Hn * Sn * DKn];     // [B,H,DK,S]  (transposed!)
__device__ float g_attn[(size_t)Bn * Sn * Dn];        // [B,S,D]

// ---------------------------------------------------------------------------
// Fast exp on the FMA pipe. Valid for x <= 0. Rel err ~1e-7.
// ---------------------------------------------------------------------------
__device__ __forceinline__ float fast_exp(float x) {
    float t = x * 1.44269504088896341f;
    t = fmaxf(t, -126.0f);
    float z = t + 12582912.0f;
    int   e = __float_as_int(z) - 0x4B400000;
    float fi = z - 12582912.0f;
    float f = t - fi;
    float p = 1.54035303933e-4f;
    p = fmaf(p, f, 1.33335581464e-3f);
    p = fmaf(p, f, 9.61812910763e-3f);
    p = fmaf(p, f, 5.55041086648e-2f);
    p = fmaf(p, f, 2.40226506959e-1f);
    p = fmaf(p, f, 6.93147180560e-1f);
    p = fmaf(p, f, 1.0f);
    return p * __int_as_float((e + 127) << 23);
}

// ---------------------------------------------------------------------------
// tf32 helpers
// ---------------------------------------------------------------------------
__device__ __forceinline__ uint32_t tf32_rna(float x) {
    uint32_t r;
    asm("cvt.rna.tf32.f32 %0, %1;" : "=r"(r) : "f"(x));
    return r;
}

__device__ __forceinline__ void mma_tf32_b(float* d, const uint32_t* a,
                                           uint32_t b0, uint32_t b1) {
    asm volatile(
        "mma.sync.aligned.m16n8k8.row.col.f32.tf32.tf32.f32 "
        "{%0,%1,%2,%3}, {%4,%5,%6,%7}, {%8,%9}, {%0,%1,%2,%3};\n"
        : "+f"(d[0]), "+f"(d[1]), "+f"(d[2]), "+f"(d[3])
        : "r"(a[0]), "r"(a[1]), "r"(a[2]), "r"(a[3]),
          "r"(b0), "r"(b1));
}

// ---------------------------------------------------------------------------
// GEMM: C[M,N] = A[M,K] @ W[N,K]^T + bias, single-pass tf32 mma m16n8k8.
// 128x128 block tile, BK=16, 256 threads, 8 warps as 2(M)x4(N) of 64x32.
// Double-buffered smem (2 stages), one barrier per k-step, LDG prefetch.
// Smem row stride 20: fragment LDS banks (4g+c+...)%32 conflict-free.
// MODE 1: write remapped: which 0->g_Q [B,H,S,DK], 1->g_K [B,H,S,DK],
//                         which 2->g_V TRANSPOSED [B,H,DK,S]
// MODE 0: A = g_attn, write plain [M,N] to outp (final projection)
// ---------------------------------------------------------------------------
#define SKW 20

template <int MODE>
__global__ __launch_bounds__(256) void gemm_k(const float* __restrict__ Ain,
                                              const float* __restrict__ W,
                                              const float* __restrict__ bias,
                                              float* __restrict__ outp,
                                              int which) {
    __shared__ __align__(16) uint32_t Ahs[2][128 * SKW];
    __shared__ __align__(16) uint32_t Whs[2][128 * SKW];

    const int tid  = threadIdx.x;
    const int lane = tid & 31;
    const int w    = tid >> 5;
    const int wm   = w >> 2;
    const int wn   = w & 3;
    const int g    = lane >> 2;
    const int c    = lane & 3;
    const int m0   = blockIdx.y << 7;
    const int n0   = blockIdx.x << 7;

    const float* A = (MODE == 0) ? g_attn : Ain;

    float acc[4][4][4];
#pragma unroll
    for (int mt = 0; mt < 4; mt++)
#pragma unroll
        for (int nt = 0; nt < 4; nt++)
#pragma unroll
            for (int r = 0; r < 4; r++) acc[mt][nt][r] = 0.f;

    const int lrow = tid >> 2;        // 0..63 (+64 on second)
    const int lq   = (tid & 3) << 2;  // 0,4,8,12

    const float* Aptr = A + (size_t)(m0 + lrow) * Dn + lq;
    const float* Wptr = W + (size_t)(n0 + lrow) * Dn + lq;

    // Prologue: load k=0 into stage 0
    {
        float4 a0 = *(const float4*)(Aptr);
        float4 a1 = *(const float4*)(Aptr + (size_t)64 * Dn);
        float4 w0 = *(const float4*)(Wptr);
        float4 w1 = *(const float4*)(Wptr + (size_t)64 * Dn);
        uint4 u;
        u.x = tf32_rna(a0.x); u.y = tf32_rna(a0.y);
        u.z = tf32_rna(a0.z); u.w = tf32_rna(a0.w);
        *(uint4*)&Ahs[0][lrow * SKW + lq] = u;
        u.x = tf32_rna(a1.x); u.y = tf32_rna(a1.y);
        u.z = tf32_rna(a1.z); u.w = tf32_rna(a1.w);
        *(uint4*)&Ahs[0][(lrow + 64) * SKW + lq] = u;
        u.x = tf32_rna(w0.x); u.y = tf32_rna(w0.y);
        u.z = tf32_rna(w0.z); u.w = tf32_rna(w0.w);
        *(uint4*)&Whs[0][lrow * SKW + lq] = u;
        u.x = tf32_rna(w1.x); u.y = tf32_rna(w1.y);
        u.z = tf32_rna(w1.z); u.w = tf32_rna(w1.w);
        *(uint4*)&Whs[0][(lrow + 64) * SKW + lq] = u;
    }
    __syncthreads();

    int s = 0;
    for (int k0 = 0; k0 < Dn; k0 += 16) {
        const bool has_next = (k0 + 16 < Dn);
        float4 na0, na1, nw0, nw1;
        if (has_next) {   // prefetch next panel into registers
            const float* ap = Aptr + k0 + 16;
            const float* wp = Wptr + k0 + 16;
            na0 = *(const float4*)(ap);
            na1 = *(const float4*)(ap + (size_t)64 * Dn);
            nw0 = *(const float4*)(wp);
            nw1 = *(const float4*)(wp + (size_t)64 * Dn);
        }

        // Compute from stage s
#pragma unroll
        for (int kk = 0; kk < 16; kk += 8) {
            uint32_t a_h[4][4], b_h[4][2];
#pragma unroll
            for (int mt = 0; mt < 4; mt++) {
                int base = ((wm << 6) + (mt << 4) + g) * SKW + kk + c;
                a_h[mt][0] = Ahs[s][base];
                a_h[mt][1] = Ahs[s][base + 8 * SKW];
                a_h[mt][2] = Ahs[s][base + 4];
                a_h[mt][3] = Ahs[s][base + 8 * SKW + 4];
            }
#pragma unroll
            for (int nt = 0; nt < 4; nt++) {
                int base = ((wn << 5) + (nt << 3) + g) * SKW + kk + c;
                b_h[nt][0] = Whs[s][base];
                b_h[nt][1] = Whs[s][base + 4];
            }
#pragma unroll
            for (int mt = 0; mt < 4; mt++)
#pragma unroll
                for (int nt = 0; nt < 4; nt++)
                    mma_tf32_b(acc[mt][nt], a_h[mt], b_h[nt][0], b_h[nt][1]);
        }

        if (has_next) {   // cvt + store prefetched panel into alternate stage
            int d = s ^ 1;
            uint4 u;
            u.x = tf32_rna(na0.x); u.y = tf32_rna(na0.y);
            u.z = tf32_rna(na0.z); u.w = tf32_rna(na0.w);
            *(uint4*)&Ahs[d][lrow * SKW + lq] = u;
            u.x = tf32_rna(na1.x); u.y = tf32_rna(na1.y);
            u.z = tf32_rna(na1.z); u.w = tf32_rna(na1.w);
            *(uint4*)&Ahs[d][(lrow + 64) * SKW + lq] = u;
            u.x = tf32_rna(nw0.x); u.y = tf32_rna(nw0.y);
            u.z = tf32_rna(nw0.z); u.w = tf32_rna(nw0.w);
            *(uint4*)&Whs[d][lrow * SKW + lq] = u;
            u.x = tf32_rna(nw1.x); u.y = tf32_rna(nw1.y);
            u.z = tf32_rna(nw1.z); u.w = tf32_rna(nw1.w);
            *(uint4*)&Whs[d][(lrow + 64) * SKW + lq] = u;
            __syncthreads();
        }
        s ^= 1;
    }

    // Epilogue
#pragma unroll
    for (int mt = 0; mt < 4; mt++) {
#pragma unroll
        for (int nt = 0; nt < 4; nt++) {
            int col = n0 + (wn << 5) + (nt << 3) + (c << 1);
            float b0 = bias[col], b1 = bias[col + 1];
#pragma unroll
            for (int half = 0; half < 2; half++) {
                int m = m0 + (wm << 6) + (mt << 4) + g + (half << 3);
                float vx = acc[mt][nt][half * 2 + 0] + b0;
                float vy = acc[mt][nt][half * 2 + 1] + b1;
                if (MODE == 1) {
                    int bb = m >> 11;
                    int ss = m & (Sn - 1);
                    int h  = col >> 6;
                    int d  = col & 63;
                    if (which == 2) {
                        // transposed: [B,H,DK,S]
                        float* outg = g_V;
                        outg[(((size_t)bb * Hn + h) * DKn + d) * Sn + ss] = vx;
                        outg[(((size_t)bb * Hn + h) * DKn + d + 1) * Sn + ss] = vy;
                    } else {
                        float* outg = (which == 0) ? g_Q : g_K;
                        float2 v = {vx, vy};
                        *(float2*)&outg[(((size_t)bb * Hn + h) * Sn + ss) * DKn + d] = v;
                    }
                } else {
                    float2 v = {vx, vy};
                    *(float2*)&outp[(size_t)m * Dn + col] = v;
                }
            }
        }
    }
}

// ---------------------------------------------------------------------------
// Flash attention on tensor cores (tf32 mma, single-pass). UNCHANGED.
// Block = 128 q rows of one (b,h); 8 warps, each owns 16 q rows (m16).
// ---------------------------------------------------------------------------
#define VSTR 68

__global__ __launch_bounds__(256, 2) void attn_kernel(const int* __restrict__ mask) {
    __shared__ __align__(16) uint32_t Ks[64 * VSTR];
    __shared__ __align__(16) uint32_t Vs[64 * VSTR];

    const int tid  = threadIdx.x;
    const int lane = tid & 31;
    const int w    = tid >> 5;
    const int g    = lane >> 2;
    const int c    = lane & 3;
    const int q0   = blockIdx.x << 7;
    const int h    = blockIdx.y;
    const int b    = blockIdx.z;

    const size_t head_off = ((size_t)b * Hn + h) * (size_t)Sn * DKn;
    const float* Qg = g_Q + head_off;
    const float* Kg = g_K + head_off;
    const float* Vg = g_V + head_off;              // [DK][S]
    const int rowA = q0 + w * 16 + g;
    const int rowB = rowA + 8;
    const int* mAp = mask + (size_t)b * Sn * Sn + (size_t)rowA * Sn;
    const int* mBp = mAp + 8 * Sn;

    uint32_t qf[8][4];
#pragma unroll
    for (int ks = 0; ks < 8; ks++) {
        qf[ks][0] = tf32_rna(Qg[(size_t)rowA * DKn + ks * 8 + c]);
        qf[ks][1] = tf32_rna(Qg[(size_t)rowB * DKn + ks * 8 + c]);
        qf[ks][2] = tf32_rna(Qg[(size_t)rowA * DKn + ks * 8 + c + 4]);
        qf[ks][3] = tf32_rna(Qg[(size_t)rowB * DKn + ks * 8 + c + 4]);
    }

    float O[8][4];
#pragma unroll
    for (int nb = 0; nb < 8; nb++)
#pragma unroll
        for (int r = 0; r < 4; r++) O[nb][r] = 0.f;
    float mxA = -1e30f, mxB = -1e30f, lA = 0.f, lB = 0.f;

    for (int kt = 0; kt < Sn / 64; kt++) {
        const int k0 = kt << 6;
        __syncthreads();

#pragma unroll
        for (int i = 0; i < 4; i++) {
            int idx = tid + (i << 8);
            int r  = idx >> 4;
            int f4 = (idx & 15) << 2;
            float4 k4 = *(const float4*)(Kg + (size_t)(k0 + r) * DKn + f4);
            uint4 uk;
            uk.x = tf32_rna(k4.x); uk.y = tf32_rna(k4.y);
            uk.z = tf32_rna(k4.z); uk.w = tf32_rna(k4.w);
            *(uint4*)&Ks[r * VSTR + f4] = uk;
            float4 v4 = *(const float4*)(Vg + (size_t)r * Sn + k0 + f4);
            uint4 uv;
            uv.x = tf32_rna(v4.x); uv.y = tf32_rna(v4.y);
            uv.z = tf32_rna(v4.z); uv.w = tf32_rna(v4.w);
            *(uint4*)&Vs[r * VSTR + f4] = uv;
        }
        __syncthreads();

        float sa[8][4];
#pragma unroll
        for (int nb = 0; nb < 8; nb++)
#pragma unroll
            for (int r = 0; r < 4; r++) sa[nb][r] = 0.f;

#pragma unroll
        for (int ks = 0; ks < 8; ks++) {
#pragma unroll
            for (int nb = 0; nb < 8; nb++) {
                uint32_t b0 = Ks[(nb * 8 + g) * VSTR + ks * 8 + c];
                uint32_t b1 = Ks[(nb * 8 + g) * VSTR + ks * 8 + c + 4];
                mma_tf32_b(sa[nb], qf[ks], b0, b1);
            }
        }

        float smA = -1e30f, smB = -1e30f;
#pragma unroll
        for (int nb = 0; nb < 8; nb++) {
            int2 m0 = *(const int2*)(mAp + k0 + nb * 8 + 2 * c);
            int2 m1 = *(const int2*)(mBp + k0 + nb * 8 + 2 * c);
            sa[nb][0] = m0.x ? sa[nb][0] * 0.125f : -1e9f;
            sa[nb][1] = m0.y ? sa[nb][1] * 0.125f : -1e9f;
            sa[nb][2] = m1.x ? sa[nb][2] * 0.125f : -1e9f;
            sa[nb][3] = m1.y ? sa[nb][3] * 0.125f : -1e9f;
            smA = fmaxf(smA, fmaxf(sa[nb][0], sa[nb][1]));
            smB = fmaxf(smB, fmaxf(sa[nb][2], sa[nb][3]));
        }
        smA = fmaxf(smA, __shfl_xor_sync(0xffffffffu, smA, 1));
        smA = fmaxf(smA, __shfl_xor_sync(0xffffffffu, smA, 2));
        smB = fmaxf(smB, __shfl_xor_sync(0xffffffffu, smB, 1));
        smB = fmaxf(smB, __shfl_xor_sync(0xffffffffu, smB, 2));

        float mnA = fmaxf(mxA, smA), mnB = fmaxf(mxB, smB);
        float aA = fast_exp(mxA - mnA), aB = fast_exp(mxB - mnB);
        mxA = mnA; mxB = mnB;

        float rsA = 0.f, rsB = 0.f;
#pragma unroll
        for (int nb = 0; nb < 8; nb++) {
            sa[nb][0] = fast_exp(sa[nb][0] - mnA);
            sa[nb][1] = fast_exp(sa[nb][1] - mnA);
            sa[nb][2] = fast_exp(sa[nb][2] - mnB);
            sa[nb][3] = fast_exp(sa[nb][3] - mnB);
            rsA += sa[nb][0] + sa[nb][1];
            rsB += sa[nb][2] + sa[nb][3];
        }
        rsA += __shfl_xor_sync(0xffffffffu, rsA, 1);
        rsA += __shfl_xor_sync(0xffffffffu, rsA, 2);
        rsB += __shfl_xor_sync(0xffffffffu, rsB, 1);
        rsB += __shfl_xor_sync(0xffffffffu, rsB, 2);
        lA = lA * aA + rsA;
        lB = lB * aB + rsB;

#pragma unroll
        for (int nb = 0; nb < 8; nb++) {
            O[nb][0] *= aA; O[nb][1] *= aA;
            O[nb][2] *= aB; O[nb][3] *= aB;
        }

        const int srcLo = (lane & 28) | (c >> 1);
        const int srcHi = srcLo + 2;
        const bool odd = (c & 1);
#pragma unroll
        for (int ks = 0; ks < 8; ks++) {
            float v0 = __shfl_sync(0xffffffffu, sa[ks][0], srcLo);
            float v1 = __shfl_sync(0xffffffffu, sa[ks][1], srcLo);
            float v2 = __shfl_sync(0xffffffffu, sa[ks][2], srcLo);
            float v3 = __shfl_sync(0xffffffffu, sa[ks][3], srcLo);
            float w0 = __shfl_sync(0xffffffffu, sa[ks][0], srcHi);
            float w1 = __shfl_sync(0xffffffffu, sa[ks][1], srcHi);
            float w2 = __shfl_sync(0xffffffffu, sa[ks][2], srcHi);
            float w3 = __shfl_sync(0xffffffffu, sa[ks][3], srcHi);
            uint32_t af[4];
            af[0] = tf32_rna(odd ? v1 : v0);
            af[1] = tf32_rna(odd ? v3 : v2);
            af[2] = tf32_rna(odd ? w1 : w0);
            af[3] = tf32_rna(odd ? w3 : w2);
#pragma unroll
            for (int nb = 0; nb < 8; nb++) {
                uint32_t b0 = Vs[(nb * 8 + g) * VSTR + ks * 8 + c];
                uint32_t b1 = Vs[(nb * 8 + g) * VSTR + ks * 8 + c + 4];
                mma_tf32_b(O[nb], af, b0, b1);
            }
        }
    }

    const float invA = 1.0f / lA, invB = 1.0f / lB;
    float* ogA = g_attn + ((size_t)b * Sn + rowA) * Dn + h * DKn;
    float* ogB = ogA + 8 * Dn;
#pragma unroll
    for (int nb = 0; nb < 8; nb++) {
        int col = nb * 8 + 2 * c;
        float2 va = {O[nb][0] * invA, O[nb][1] * invA};
        float2 vb = {O[nb][2] * invB, O[nb][3] * invB};
        *(float2*)&ogA[col] = va;
        *(float2*)&ogB[col] = vb;
    }
}

// ---------------------------------------------------------------------------
// kernel_launch: 5 kernel launches on the default stream (graph-capturable)
// ---------------------------------------------------------------------------
extern "C" void kernel_launch(void* const* d_in, const int* in_sizes, int n_in,
                              void* d_out, int out_size) {
    (void)in_sizes; (void)n_in; (void)out_size;
    const float* query = (const float*)d_in[0];
    const float* key   = (const float*)d_in[1];
    const float* value = (const float*)d_in[2];
    const int*   mask  = (const int*)d_in[3];
    const float* Wq = (const float*)d_in[4];
    const float* bq = (const float*)d_in[5];
    const float* Wk = (const float*)d_in[6];
    const float* bk = (const float*)d_in[7];
    const float* Wv = (const float*)d_in[8];
    const float* bv = (const float*)d_in[9];
    const float* Wo = (const float*)d_in[10];
    const float* bo = (const float*)d_in[11];

    dim3 gg(Dn / 128, Mn / 128);   // (8, 64)
    gemm_k<1><<<gg, 256>>>(query, Wq, bq, nullptr, 0);
    gemm_k<1><<<gg, 256>>>(key,   Wk, bk, nullptr, 1);
    gemm_k<1><<<gg, 256>>>(value, Wv, bv, nullptr, 2);

    attn_kernel<<<dim3(Sn / 128, Hn, Bn), 256>>>(mask);

    gemm_k<0><<<gg, 256>>>(nullptr, Wo, bo, (float*)d_out, 0);
}

// round 9
// speedup vs baseline: 3.0296x; 1.0002x over previous
#include <cuda_runtime.h>
#include <cstdint>

// Problem constants
#define Bn  4
#define Sn  2048
#define Dn  1024
#define Hn  16
#define DKn 64
#define Mn  (Bn * Sn)   // 8192

// Scratch (allocation-free: __device__ globals)
__device__ float g_Q[(size_t)Bn * Hn * Sn * DKn];     // [B,H,S,DK]
__device__ float g_K[(size_t)Bn * Hn * Sn * DKn];     // [B,H,S,DK]
__device__ float g_V[(size_t)Bn * Hn * Sn * DKn];     // [B,H,DK,S]  (transposed!)
__device__ float g_attn[(size_t)Bn * Sn * Dn];        // [B,S,D]

// ---------------------------------------------------------------------------
// Fast exp on the FMA pipe. Valid for x <= 0. Rel err ~1e-7.
// ---------------------------------------------------------------------------
__device__ __forceinline__ float fast_exp(float x) {
    float t = x * 1.44269504088896341f;
    t = fmaxf(t, -126.0f);
    float z = t + 12582912.0f;
    int   e = __float_as_int(z) - 0x4B400000;
    float fi = z - 12582912.0f;
    float f = t - fi;
    float p = 1.54035303933e-4f;
    p = fmaf(p, f, 1.33335581464e-3f);
    p = fmaf(p, f, 9.61812910763e-3f);
    p = fmaf(p, f, 5.55041086648e-2f);
    p = fmaf(p, f, 2.40226506959e-1f);
    p = fmaf(p, f, 6.93147180560e-1f);
    p = fmaf(p, f, 1.0f);
    return p * __int_as_float((e + 127) << 23);
}

// ---------------------------------------------------------------------------
// tf32 helpers
// ---------------------------------------------------------------------------
__device__ __forceinline__ uint32_t tf32_rna(float x) {
    uint32_t r;
    asm("cvt.rna.tf32.f32 %0, %1;" : "=r"(r) : "f"(x));
    return r;
}

__device__ __forceinline__ void mma_tf32_b(float* d, const uint32_t* a,
                                           uint32_t b0, uint32_t b1) {
    asm volatile(
        "mma.sync.aligned.m16n8k8.row.col.f32.tf32.tf32.f32 "
        "{%0,%1,%2,%3}, {%4,%5,%6,%7}, {%8,%9}, {%0,%1,%2,%3};\n"
        : "+f"(d[0]), "+f"(d[1]), "+f"(d[2]), "+f"(d[3])
        : "r"(a[0]), "r"(a[1]), "r"(a[2]), "r"(a[3]),
          "r"(b0), "r"(b1));
}

// ---------------------------------------------------------------------------
// GEMM: C[M,N] = A[M,K] @ W[N,K]^T + bias, single-pass tf32 mma m16n8k8.
// 128x128 block tile, BK=16, 256 threads, 8 warps as 2(M)x4(N) of 64x32.
// Double-buffered smem (2 stages), one barrier per k-step, LDG prefetch.
// Smem row stride 20: fragment LDS banks (4g+c+...)%32 conflict-free.
// MODE 1: write remapped: which 0->g_Q [B,H,S,DK], 1->g_K [B,H,S,DK],
//                         which 2->g_V TRANSPOSED [B,H,DK,S]
// MODE 0: A = g_attn, write plain [M,N] to outp (final projection)
// ---------------------------------------------------------------------------
#define SKW 20

template <int MODE>
__global__ __launch_bounds__(256) void gemm_k(const float* __restrict__ Ain,
                                              const float* __restrict__ W,
                                              const float* __restrict__ bias,
                                              float* __restrict__ outp,
                                              int which) {
    __shared__ __align__(16) uint32_t Ahs[2][128 * SKW];
    __shared__ __align__(16) uint32_t Whs[2][128 * SKW];

    const int tid  = threadIdx.x;
    const int lane = tid & 31;
    const int w    = tid >> 5;
    const int wm   = w >> 2;
    const int wn   = w & 3;
    const int g    = lane >> 2;
    const int c    = lane & 3;
    const int m0   = blockIdx.y << 7;
    const int n0   = blockIdx.x << 7;

    const float* A = (MODE == 0) ? g_attn : Ain;

    float acc[4][4][4];
#pragma unroll
    for (int mt = 0; mt < 4; mt++)
#pragma unroll
        for (int nt = 0; nt < 4; nt++)
#pragma unroll
            for (int r = 0; r < 4; r++) acc[mt][nt][r] = 0.f;

    const int lrow = tid >> 2;        // 0..63 (+64 on second)
    const int lq   = (tid & 3) << 2;  // 0,4,8,12

    const float* Aptr = A + (size_t)(m0 + lrow) * Dn + lq;
    const float* Wptr = W + (size_t)(n0 + lrow) * Dn + lq;

    // Prologue: load k=0 into stage 0
    {
        float4 a0 = *(const float4*)(Aptr);
        float4 a1 = *(const float4*)(Aptr + (size_t)64 * Dn);
        float4 w0 = *(const float4*)(Wptr);
        float4 w1 = *(const float4*)(Wptr + (size_t)64 * Dn);
        uint4 u;
        u.x = tf32_rna(a0.x); u.y = tf32_rna(a0.y);
        u.z = tf32_rna(a0.z); u.w = tf32_rna(a0.w);
        *(uint4*)&Ahs[0][lrow * SKW + lq] = u;
        u.x = tf32_rna(a1.x); u.y = tf32_rna(a1.y);
        u.z = tf32_rna(a1.z); u.w = tf32_rna(a1.w);
        *(uint4*)&Ahs[0][(lrow + 64) * SKW + lq] = u;
        u.x = tf32_rna(w0.x); u.y = tf32_rna(w0.y);
        u.z = tf32_rna(w0.z); u.w = tf32_rna(w0.w);
        *(uint4*)&Whs[0][lrow * SKW + lq] = u;
        u.x = tf32_rna(w1.x); u.y = tf32_rna(w1.y);
        u.z = tf32_rna(w1.z); u.w = tf32_rna(w1.w);
        *(uint4*)&Whs[0][(lrow + 64) * SKW + lq] = u;
    }
    __syncthreads();

    int s = 0;
    for (int k0 = 0; k0 < Dn; k0 += 16) {
        const bool has_next = (k0 + 16 < Dn);
        float4 na0, na1, nw0, nw1;
        if (has_next) {   // prefetch next panel into registers
            const float* ap = Aptr + k0 + 16;
            const float* wp = Wptr + k0 + 16;
            na0 = *(const float4*)(ap);
            na1 = *(const float4*)(ap + (size_t)64 * Dn);
            nw0 = *(const float4*)(wp);
            nw1 = *(const float4*)(wp + (size_t)64 * Dn);
        }

        // Compute from stage s
#pragma unroll
        for (int kk = 0; kk < 16; kk += 8) {
            uint32_t a_h[4][4], b_h[4][2];
#pragma unroll
            for (int mt = 0; mt < 4; mt++) {
                int base = ((wm << 6) + (mt << 4) + g) * SKW + kk + c;
                a_h[mt][0] = Ahs[s][base];
                a_h[mt][1] = Ahs[s][base + 8 * SKW];
                a_h[mt][2] = Ahs[s][base + 4];
                a_h[mt][3] = Ahs[s][base + 8 * SKW + 4];
            }
#pragma unroll
            for (int nt = 0; nt < 4; nt++) {
                int base = ((wn << 5) + (nt << 3) + g) * SKW + kk + c;
                b_h[nt][0] = Whs[s][base];
                b_h[nt][1] = Whs[s][base + 4];
            }
#pragma unroll
            for (int mt = 0; mt < 4; mt++)
#pragma unroll
                for (int nt = 0; nt < 4; nt++)
                    mma_tf32_b(acc[mt][nt], a_h[mt], b_h[nt][0], b_h[nt][1]);
        }

        if (has_next) {   // cvt + store prefetched panel into alternate stage
            int d = s ^ 1;
            uint4 u;
            u.x = tf32_rna(na0.x); u.y = tf32_rna(na0.y);
            u.z = tf32_rna(na0.z); u.w = tf32_rna(na0.w);
            *(uint4*)&Ahs[d][lrow * SKW + lq] = u;
            u.x = tf32_rna(na1.x); u.y = tf32_rna(na1.y);
            u.z = tf32_rna(na1.z); u.w = tf32_rna(na1.w);
            *(uint4*)&Ahs[d][(lrow + 64) * SKW + lq] = u;
            u.x = tf32_rna(nw0.x); u.y = tf32_rna(nw0.y);
            u.z = tf32_rna(nw0.z); u.w = tf32_rna(nw0.w);
            *(uint4*)&Whs[d][lrow * SKW + lq] = u;
            u.x = tf32_rna(nw1.x); u.y = tf32_rna(nw1.y);
            u.z = tf32_rna(nw1.z); u.w = tf32_rna(nw1.w);
            *(uint4*)&Whs[d][(lrow + 64) * SKW + lq] = u;
            __syncthreads();
        }
        s ^= 1;
    }

    // Epilogue
#pragma unroll
    for (int mt = 0; mt < 4; mt++) {
#pragma unroll
        for (int nt = 0; nt < 4; nt++) {
            int col = n0 + (wn << 5) + (nt << 3) + (c << 1);
            float b0 = bias[col], b1 = bias[col + 1];
#pragma unroll
            for (int half = 0; half < 2; half++) {
                int m = m0 + (wm << 6) + (mt << 4) + g + (half << 3);
                float vx = acc[mt][nt][half * 2 + 0] + b0;
                float vy = acc[mt][nt][half * 2 + 1] + b1;
                if (MODE == 1) {
                    int bb = m >> 11;
                    int ss = m & (Sn - 1);
                    int h  = col >> 6;
                    int d  = col & 63;
                    if (which == 2) {
                        // transposed: [B,H,DK,S]
                        float* outg = g_V;
                        outg[(((size_t)bb * Hn + h) * DKn + d) * Sn + ss] = vx;
                        outg[(((size_t)bb * Hn + h) * DKn + d + 1) * Sn + ss] = vy;
                    } else {
                        float* outg = (which == 0) ? g_Q : g_K;
                        float2 v = {vx, vy};
                        *(float2*)&outg[(((size_t)bb * Hn + h) * Sn + ss) * DKn + d] = v;
                    }
                } else {
                    float2 v = {vx, vy};
                    *(float2*)&outp[(size_t)m * Dn + col] = v;
                }
            }
        }
    }
}

// ---------------------------------------------------------------------------
// Flash attention on tensor cores (tf32 mma, single-pass). UNCHANGED.
// Block = 128 q rows of one (b,h); 8 warps, each owns 16 q rows (m16).
// ---------------------------------------------------------------------------
#define VSTR 68

__global__ __launch_bounds__(256, 2) void attn_kernel(const int* __restrict__ mask) {
    __shared__ __align__(16) uint32_t Ks[64 * VSTR];
    __shared__ __align__(16) uint32_t Vs[64 * VSTR];

    const int tid  = threadIdx.x;
    const int lane = tid & 31;
    const int w    = tid >> 5;
    const int g    = lane >> 2;
    const int c    = lane & 3;
    const int q0   = blockIdx.x << 7;
    const int h    = blockIdx.y;
    const int b    = blockIdx.z;

    const size_t head_off = ((size_t)b * Hn + h) * (size_t)Sn * DKn;
    const float* Qg = g_Q + head_off;
    const float* Kg = g_K + head_off;
    const float* Vg = g_V + head_off;              // [DK][S]
    const int rowA = q0 + w * 16 + g;
    const int rowB = rowA + 8;
    const int* mAp = mask + (size_t)b * Sn * Sn + (size_t)rowA * Sn;
    const int* mBp = mAp + 8 * Sn;

    uint32_t qf[8][4];
#pragma unroll
    for (int ks = 0; ks < 8; ks++) {
        qf[ks][0] = tf32_rna(Qg[(size_t)rowA * DKn + ks * 8 + c]);
        qf[ks][1] = tf32_rna(Qg[(size_t)rowB * DKn + ks * 8 + c]);
        qf[ks][2] = tf32_rna(Qg[(size_t)rowA * DKn + ks * 8 + c + 4]);
        qf[ks][3] = tf32_rna(Qg[(size_t)rowB * DKn + ks * 8 + c + 4]);
    }

    float O[8][4];
#pragma unroll
    for (int nb = 0; nb < 8; nb++)
#pragma unroll
        for (int r = 0; r < 4; r++) O[nb][r] = 0.f;
    float mxA = -1e30f, mxB = -1e30f, lA = 0.f, lB = 0.f;

    for (int kt = 0; kt < Sn / 64; kt++) {
        const int k0 = kt << 6;
        __syncthreads();

#pragma unroll
        for (int i = 0; i < 4; i++) {
            int idx = tid + (i << 8);
            int r  = idx >> 4;
            int f4 = (idx & 15) << 2;
            float4 k4 = *(const float4*)(Kg + (size_t)(k0 + r) * DKn + f4);
            uint4 uk;
            uk.x = tf32_rna(k4.x); uk.y = tf32_rna(k4.y);
            uk.z = tf32_rna(k4.z); uk.w = tf32_rna(k4.w);
            *(uint4*)&Ks[r * VSTR + f4] = uk;
            float4 v4 = *(const float4*)(Vg + (size_t)r * Sn + k0 + f4);
            uint4 uv;
            uv.x = tf32_rna(v4.x); uv.y = tf32_rna(v4.y);
            uv.z = tf32_rna(v4.z); uv.w = tf32_rna(v4.w);
            *(uint4*)&Vs[r * VSTR + f4] = uv;
        }
        __syncthreads();

        float sa[8][4];
#pragma unroll
        for (int nb = 0; nb < 8; nb++)
#pragma unroll
            for (int r = 0; r < 4; r++) sa[nb][r] = 0.f;

#pragma unroll
        for (int ks = 0; ks < 8; ks++) {
#pragma unroll
            for (int nb = 0; nb < 8; nb++) {
                uint32_t b0 = Ks[(nb * 8 + g) * VSTR + ks * 8 + c];
                uint32_t b1 = Ks[(nb * 8 + g) * VSTR + ks * 8 + c + 4];
                mma_tf32_b(sa[nb], qf[ks], b0, b1);
            }
        }

        float smA = -1e30f, smB = -1e30f;
#pragma unroll
        for (int nb = 0; nb < 8; nb++) {
            int2 m0 = *(const int2*)(mAp + k0 + nb * 8 + 2 * c);
            int2 m1 = *(const int2*)(mBp + k0 + nb * 8 + 2 * c);
            sa[nb][0] = m0.x ? sa[nb][0] * 0.125f : -1e9f;
            sa[nb][1] = m0.y ? sa[nb][1] * 0.125f : -1e9f;
            sa[nb][2] = m1.x ? sa[nb][2] * 0.125f : -1e9f;
            sa[nb][3] = m1.y ? sa[nb][3] * 0.125f : -1e9f;
            smA = fmaxf(smA, fmaxf(sa[nb][0], sa[nb][1]));
            smB = fmaxf(smB, fmaxf(sa[nb][2], sa[nb][3]));
        }
        smA = fmaxf(smA, __shfl_xor_sync(0xffffffffu, smA, 1));
        smA = fmaxf(smA, __shfl_xor_sync(0xffffffffu, smA, 2));
        smB = fmaxf(smB, __shfl_xor_sync(0xffffffffu, smB, 1));
        smB = fmaxf(smB, __shfl_xor_sync(0xffffffffu, smB, 2));

        float mnA = fmaxf(mxA, smA), mnB = fmaxf(mxB, smB);
        float aA = fast_exp(mxA - mnA), aB = fast_exp(mxB - mnB);
        mxA = mnA; mxB = mnB;

        float rsA = 0.f, rsB = 0.f;
#pragma unroll
        for (int nb = 0; nb < 8; nb++) {
            sa[nb][0] = fast_exp(sa[nb][0] - mnA);
            sa[nb][1] = fast_exp(sa[nb][1] - mnA);
            sa[nb][2] = fast_exp(sa[nb][2] - mnB);
            sa[nb][3] = fast_exp(sa[nb][3] - mnB);
            rsA += sa[nb][0] + sa[nb][1];
            rsB += sa[nb][2] + sa[nb][3];
        }
        rsA += __shfl_xor_sync(0xffffffffu, rsA, 1);
        rsA += __shfl_xor_sync(0xffffffffu, rsA, 2);
        rsB += __shfl_xor_sync(0xffffffffu, rsB, 1);
        rsB += __shfl_xor_sync(0xffffffffu, rsB, 2);
        lA = lA * aA + rsA;
        lB = lB * aB + rsB;

#pragma unroll
        for (int nb = 0; nb < 8; nb++) {
            O[nb][0] *= aA; O[nb][1] *= aA;
            O[nb][2] *= aB; O[nb][3] *= aB;
        }

        const int srcLo = (lane & 28) | (c >> 1);
        const int srcHi = srcLo + 2;
        const bool odd = (c & 1);
#pragma unroll
        for (int ks = 0; ks < 8; ks++) {
            float v0 = __shfl_sync(0xffffffffu, sa[ks][0], srcLo);
            float v1 = __shfl_sync(0xffffffffu, sa[ks][1], srcLo);
            float v2 = __shfl_sync(0xffffffffu, sa[ks][2], srcLo);
            float v3 = __shfl_sync(0xffffffffu, sa[ks][3], srcLo);
            float w0 = __shfl_sync(0xffffffffu, sa[ks][0], srcHi);
            float w1 = __shfl_sync(0xffffffffu, sa[ks][1], srcHi);
            float w2 = __shfl_sync(0xffffffffu, sa[ks][2], srcHi);
            float w3 = __shfl_sync(0xffffffffu, sa[ks][3], srcHi);
            uint32_t af[4];
            af[0] = tf32_rna(odd ? v1 : v0);
            af[1] = tf32_rna(odd ? v3 : v2);
            af[2] = tf32_rna(odd ? w1 : w0);
            af[3] = tf32_rna(odd ? w3 : w2);
#pragma unroll
            for (int nb = 0; nb < 8; nb++) {
                uint32_t b0 = Vs[(nb * 8 + g) * VSTR + ks * 8 + c];
                uint32_t b1 = Vs[(nb * 8 + g) * VSTR + ks * 8 + c + 4];
                mma_tf32_b(O[nb], af, b0, b1);
            }
        }
    }

    const float invA = 1.0f / lA, invB = 1.0f / lB;
    float* ogA = g_attn + ((size_t)b * Sn + rowA) * Dn + h * DKn;
    float* ogB = ogA + 8 * Dn;
#pragma unroll
    for (int nb = 0; nb < 8; nb++) {
        int col = nb * 8 + 2 * c;
        float2 va = {O[nb][0] * invA, O[nb][1] * invA};
        float2 vb = {O[nb][2] * invB, O[nb][3] * invB};
        *(float2*)&ogA[col] = va;
        *(float2*)&ogB[col] = vb;
    }
}

// ---------------------------------------------------------------------------
// kernel_launch: 5 kernel launches on the default stream (graph-capturable)
// ---------------------------------------------------------------------------
extern "C" void kernel_launch(void* const* d_in, const int* in_sizes, int n_in,
                              void* d_out, int out_size) {
    (void)in_sizes; (void)n_in; (void)out_size;
    const float* query = (const float*)d_in[0];
    const float* key   = (const float*)d_in[1];
    const float* value = (const float*)d_in[2];
    const int*   mask  = (const int*)d_in[3];
    const float* Wq = (const float*)d_in[4];
    const float* bq = (const float*)d_in[5];
    const float* Wk = (const float*)d_in[6];
    const float* bk = (const float*)d_in[7];
    const float* Wv = (const float*)d_in[8];
    const float* bv = (const float*)d_in[9];
    const float* Wo = (const float*)d_in[10];
    const float* bo = (const float*)d_in[11];

    dim3 gg(Dn / 128, Mn / 128);   // (8, 64)
    gemm_k<1><<<gg, 256>>>(query, Wq, bq, nullptr, 0);
    gemm_k<1><<<gg, 256>>>(key,   Wk, bk, nullptr, 1);
    gemm_k<1><<<gg, 256>>>(value, Wv, bv, nullptr, 2);

    attn_kernel<<<dim3(Sn / 128, Hn, Bn), 256>>>(mask);

    gemm_k<0><<<gg, 256>>>(nullptr, Wo, bo, (float*)d_out, 0);
}